// round 2
// baseline (speedup 1.0000x reference)
#include <cuda_runtime.h>
#include <math.h>

#define NODES 8672
#define ND    2528      // drug nodes (32*79)
#define NP    6144      // protein nodes (32*192)
#define HIDD  128
#define BSZ   32
#define LL1   79
#define LL2   192
#define E1T   5120
#define E2T   12800
#define ETOT  17920
#define SEIN  15168
#define SEHID 2000

// ---------------- device scratch ----------------
__device__ float g_emb0[NODES*HIDD];
__device__ float g_x   [NODES*HIDD];   // current GAT input
__device__ float g_h   [NODES*HIDD];   // h = x @ W
__device__ float g_o   [NODES*HIDD];   // GAT layer output accumulator
__device__ float g_xsum[NODES*HIDD];   // x11+x12+x13 / x21+x22+x23
__device__ float g_hs[NODES], g_hd[NODES], g_m[NODES], g_den[NODES];
__device__ float g_rs[NODES];          // per-node feature row sums
__device__ float g_c [BSZ*SEIN];
__device__ float g_c1[BSZ*SEHID];
__device__ float g_c2[BSZ*SEIN];
__device__ float g_wl[BSZ*LL1], g_wp[BSZ*LL2];
__device__ float g_xx[BSZ*256];
__device__ float g_f1[BSZ*512], g_f2[BSZ*256], g_f3[BSZ*128], g_f4[BSZ*64];

__device__ __forceinline__ float lrelu(float x) { return x > 0.f ? x : 0.2f * x; }

__device__ __forceinline__ void edge_sd(int idx, const int* dei, const int* pei, int& s, int& d) {
    if (idx < E1T) { s = dei[idx]; d = dei[E1T + idx]; }
    else { int e = idx - E1T; s = pei[e] + ND; d = pei[E2T + e] + ND; }
}

__device__ __forceinline__ void atomicMaxFloat(float* addr, float val) {
    int* ia = (int*)addr;
    int old = *ia;
    while (__int_as_float(old) < val) {
        int assumed = old;
        old = atomicCAS(ia, assumed, __float_as_int(val));
        if (old == assumed) break;
    }
}

// ---------------- embedding MLP ----------------
__global__ void k_embed1(const float* __restrict__ x1, const float* __restrict__ x2,
                         const float* __restrict__ w1, const float* __restrict__ b1) {
    int row = blockIdx.x, t = threadIdx.x;
    __shared__ float xs[52];
    const float* x = (row < ND) ? (x1 + (size_t)row * 52) : (x2 + (size_t)(row - ND) * 52);
    if (t < 52) xs[t] = x[t];
    __syncthreads();
    float acc = b1[t];
#pragma unroll
    for (int k = 0; k < 52; k++) acc = fmaf(xs[k], w1[k * HIDD + t], acc);
    g_emb0[row * HIDD + t] = fmaxf(acc, 0.f);
}

__global__ void k_embed2(const float* __restrict__ w2, const float* __restrict__ b2) {
    int row = blockIdx.x, t = threadIdx.x;
    __shared__ float xs[HIDD];
    xs[t] = g_emb0[row * HIDD + t];
    __syncthreads();
    float acc = b2[t];
#pragma unroll
    for (int k = 0; k < HIDD; k++) acc = fmaf(xs[k], w2[k * HIDD + t], acc);
    g_x[row * HIDD + t] = fmaxf(acc, 0.f);
}

// ---------------- GAT: h = x@W plus attention dots ----------------
__global__ void k_gat_h(const float* __restrict__ gat_w, const float* __restrict__ gat_as,
                        const float* __restrict__ gat_ad, int layer) {
    int r0 = blockIdx.x * 4;
    int t = threadIdx.x;
    __shared__ float xs[4][HIDD];
    __shared__ float red[HIDD], red2[HIDD];
#pragma unroll
    for (int r = 0; r < 4; r++) xs[r][t] = g_x[(r0 + r) * HIDD + t];
    __syncthreads();
    int widx = (r0 < ND) ? layer : 3 + layer;   // ND divisible by 4: no straddle
    const float* W = gat_w + (size_t)widx * HIDD * HIDD;
    float acc[4] = {0.f, 0.f, 0.f, 0.f};
    for (int k = 0; k < HIDD; k++) {
        float w = W[k * HIDD + t];
#pragma unroll
        for (int r = 0; r < 4; r++) acc[r] = fmaf(xs[r][k], w, acc[r]);
    }
    float as = gat_as[widx * HIDD + t], ad = gat_ad[widx * HIDD + t];
#pragma unroll
    for (int r = 0; r < 4; r++) g_h[(r0 + r) * HIDD + t] = acc[r];
    for (int r = 0; r < 4; r++) {
        red[t]  = acc[r] * as;
        red2[t] = acc[r] * ad;
        __syncthreads();
        for (int s = 64; s > 0; s >>= 1) {
            if (t < s) { red[t] += red[t + s]; red2[t] += red2[t + s]; }
            __syncthreads();
        }
        if (t == 0) { g_hs[r0 + r] = red[0]; g_hd[r0 + r] = red2[0]; }
        __syncthreads();
    }
}

__global__ void k_init_m() {
    int n = blockIdx.x * blockDim.x + threadIdx.x;
    if (n < NODES) g_m[n] = lrelu(g_hs[n] + g_hd[n]);   // self-loop value
}

__global__ void k_edge_max(const int* __restrict__ dei, const int* __restrict__ pei) {
    int idx = blockIdx.x * blockDim.x + threadIdx.x;
    if (idx >= ETOT) return;
    int s, d; edge_sd(idx, dei, pei, s, d);
    atomicMaxFloat(&g_m[d], lrelu(g_hs[s] + g_hd[d]));
}

__global__ void k_self_den() {
    int n = blockIdx.x * blockDim.x + threadIdx.x;
    if (n < NODES) g_den[n] = expf(lrelu(g_hs[n] + g_hd[n]) - g_m[n]);
}

__global__ void k_edge_den(const int* __restrict__ dei, const int* __restrict__ pei) {
    int idx = blockIdx.x * blockDim.x + threadIdx.x;
    if (idx >= ETOT) return;
    int s, d; edge_sd(idx, dei, pei, s, d);
    atomicAdd(&g_den[d], expf(lrelu(g_hs[s] + g_hd[d]) - g_m[d]));
}

__global__ void k_self_out(const float* __restrict__ gat_b, int layer) {
    int idx = blockIdx.x * blockDim.x + threadIdx.x;
    if (idx >= NODES * HIDD) return;
    int n = idx >> 7, t = idx & 127;
    int widx = (n < ND) ? layer : 3 + layer;
    float alpha = expf(lrelu(g_hs[n] + g_hd[n]) - g_m[n]) / g_den[n];
    g_o[idx] = gat_b[widx * HIDD + t] + alpha * g_h[idx];
}

__global__ void k_edge_out(const int* __restrict__ dei, const int* __restrict__ pei) {
    int gid = blockIdx.x * blockDim.x + threadIdx.x;
    int e = gid >> 5, lane = gid & 31;
    if (e >= ETOT) return;
    int s, d; edge_sd(e, dei, pei, s, d);
    float alpha = 0.f;
    if (lane == 0) alpha = expf(lrelu(g_hs[s] + g_hd[d]) - g_m[d]) / g_den[d];
    alpha = __shfl_sync(0xffffffffu, alpha, 0);
#pragma unroll
    for (int f = lane; f < HIDD; f += 32)
        atomicAdd(&g_o[d * HIDD + f], alpha * g_h[s * HIDD + f]);
}

__global__ void k_relu_accum(int layer) {
    int idx = blockIdx.x * blockDim.x + threadIdx.x;
    if (idx >= NODES * HIDD) return;
    float v = fmaxf(g_o[idx], 0.f);
    g_x[idx] = v;
    g_xsum[idx] = (layer == 0) ? v : (g_xsum[idx] + v);
}

// ---------------- cross fusion ----------------
__global__ void k_rowsum() {
    int gid = blockIdx.x * blockDim.x + threadIdx.x;
    int n = gid >> 5, lane = gid & 31;
    if (n >= NODES) return;
    float s = 0.f;
#pragma unroll
    for (int k = 0; k < 4; k++) s += g_xsum[n * HIDD + lane + 32 * k];
#pragma unroll
    for (int o = 16; o > 0; o >>= 1) s += __shfl_down_sync(0xffffffffu, s, o);
    if (lane == 0) g_rs[n] = s;
}

__global__ void k_cbuf() {
    int idx = blockIdx.x * blockDim.x + threadIdx.x;
    if (idx >= BSZ * SEIN) return;
    int b = idx / SEIN, r = idx % SEIN;
    int i = r / LL2, j = r % LL2;
    g_c[idx] = (g_rs[b * LL1 + i] + g_rs[ND + b * LL2 + j]) * (1.f / 256.f);
}

__global__ void k_initbias(float* __restrict__ C, const float* __restrict__ bias, int N) {
    int idx = blockIdx.x * blockDim.x + threadIdx.x;
    if (idx < BSZ * N) C[idx] = bias[idx % N];
}

// skinny GEMM: C(32,N) += A(32,K) @ W(K,N), split-K via atomics
__global__ void k_skinny(const float* __restrict__ A, const float* __restrict__ W,
                         float* __restrict__ C, int K, int N) {
    const int TK = 32;
    int n = blockIdx.x * blockDim.x + threadIdx.x;
    int kchunk = (K + gridDim.y - 1) / gridDim.y;
    int k0 = blockIdx.y * kchunk;
    int k1 = min(K, k0 + kchunk);
    __shared__ float As[32 * TK];
    float acc[32];
#pragma unroll
    for (int m = 0; m < 32; m++) acc[m] = 0.f;
    for (int kk = k0; kk < k1; kk += TK) {
        int tkl = min(TK, k1 - kk);
        for (int idx = threadIdx.x; idx < 32 * tkl; idx += blockDim.x) {
            int m = idx / tkl, t = idx % tkl;
            As[m * TK + t] = A[(size_t)m * K + kk + t];
        }
        __syncthreads();
        if (n < N) {
            for (int t = 0; t < tkl; t++) {
                float w = W[(size_t)(kk + t) * N + n];
#pragma unroll
                for (int m = 0; m < 32; m++) acc[m] = fmaf(As[m * TK + t], w, acc[m]);
            }
        }
        __syncthreads();
    }
    if (n < N)
#pragma unroll
        for (int m = 0; m < 32; m++) atomicAdd(&C[(size_t)m * N + n], acc[m]);
}

__global__ void k_act(float* __restrict__ p, int n, int mode) {
    int idx = blockIdx.x * blockDim.x + threadIdx.x;
    if (idx >= n) return;
    float v = p[idx];
    p[idx] = (mode == 1) ? fmaxf(v, 0.f) : 1.f / (1.f + expf(-v));
}

__global__ void k_wl(const float* __restrict__ inter) {
    int gid = blockIdx.x * blockDim.x + threadIdx.x;
    int bi = gid >> 5, lane = gid & 31;
    if (bi >= BSZ * LL1) return;
    int b = bi / LL1, i = bi % LL1;
    float s = 0.f;
    for (int j = lane; j < LL2; j += 32) {
        int idx = b * SEIN + i * LL2 + j;
        s += g_c2[idx] / inter[idx];
    }
#pragma unroll
    for (int o = 16; o > 0; o >>= 1) s += __shfl_down_sync(0xffffffffu, s, o);
    if (lane == 0) g_wl[bi] = s * (1.f / (float)SEIN);
}

__global__ void k_wp(const float* __restrict__ inter) {
    int gid = blockIdx.x * blockDim.x + threadIdx.x;
    int bj = gid >> 5, lane = gid & 31;
    if (bj >= BSZ * LL2) return;
    int b = bj / LL2, j = bj % LL2;
    float s = 0.f;
    for (int i = lane; i < LL1; i += 32) {
        int idx = b * SEIN + i * LL2 + j;
        s += g_c2[idx] / inter[idx];
    }
#pragma unroll
    for (int o = 16; o > 0; o >>= 1) s += __shfl_down_sync(0xffffffffu, s, o);
    if (lane == 0) g_wp[bj] = s * (1.f / (float)SEIN);
}

__global__ void k_fuse() {
    int b = blockIdx.x, t = threadIdx.x;
    float acc = 0.f;
    if (t < HIDD) {
        for (int i = 0; i < LL1; i++)
            acc += g_wl[b * LL1 + i] * g_xsum[(b * LL1 + i) * HIDD + t];
    } else {
        int h = t - HIDD;
        for (int j = 0; j < LL2; j++)
            acc += g_wp[b * LL2 + j] * g_xsum[(ND + b * LL2 + j) * HIDD + h];
    }
    g_xx[b * 256 + t] = acc;
}

// ---------------- head MLP ----------------
__global__ void k_dense(const float* __restrict__ in, const float* __restrict__ W,
                        const float* __restrict__ bias, float* __restrict__ out_pre,
                        float* __restrict__ out_act, int K, int N, int act) {
    int row = blockIdx.x;
    __shared__ float xs[512];
    for (int k = threadIdx.x; k < K; k += blockDim.x) xs[k] = in[row * K + k];
    __syncthreads();
    for (int n = threadIdx.x; n < N; n += blockDim.x) {
        float acc = bias[n];
        for (int k = 0; k < K; k++) acc = fmaf(xs[k], W[k * N + n], acc);
        if (out_pre) out_pre[row * N + n] = acc;
        if (act == 1) acc = fmaxf(acc, 0.f);
        if (out_act) out_act[row * N + n] = acc;
    }
}

extern "C" void kernel_launch(void* const* d_in, const int* in_sizes, int n_in,
                              void* d_out, int out_size) {
    const float* x1    = (const float*)d_in[0];
    const float* x2    = (const float*)d_in[1];
    const float* inter = (const float*)d_in[2];
    const int*   dei   = (const int*)d_in[3];
    const int*   pei   = (const int*)d_in[4];
    const float* w1    = (const float*)d_in[5];
    const float* b1    = (const float*)d_in[6];
    const float* w2    = (const float*)d_in[7];
    const float* b2    = (const float*)d_in[8];
    const float* gat_w = (const float*)d_in[9];
    const float* gat_as= (const float*)d_in[10];
    const float* gat_ad= (const float*)d_in[11];
    const float* gat_b = (const float*)d_in[12];
    const float* se1_w = (const float*)d_in[13];
    const float* se1_b = (const float*)d_in[14];
    const float* se2_w = (const float*)d_in[15];
    const float* se2_b = (const float*)d_in[16];
    const float* fc1_w = (const float*)d_in[17];
    const float* fc1_b = (const float*)d_in[18];
    const float* fc2_w = (const float*)d_in[19];
    const float* fc2_b = (const float*)d_in[20];
    const float* fc3_w = (const float*)d_in[21];
    const float* fc3_b = (const float*)d_in[22];
    const float* fc4_w = (const float*)d_in[23];
    const float* fc4_b = (const float*)d_in[24];
    const float* out_w = (const float*)d_in[25];
    const float* out_b = (const float*)d_in[26];
    float* dout = (float*)d_out;

    float *pc, *pc1, *pc2, *pxx, *pf1, *pf2, *pf3, *pf4;
    cudaGetSymbolAddress((void**)&pc,  g_c);
    cudaGetSymbolAddress((void**)&pc1, g_c1);
    cudaGetSymbolAddress((void**)&pc2, g_c2);
    cudaGetSymbolAddress((void**)&pxx, g_xx);
    cudaGetSymbolAddress((void**)&pf1, g_f1);
    cudaGetSymbolAddress((void**)&pf2, g_f2);
    cudaGetSymbolAddress((void**)&pf3, g_f3);
    cudaGetSymbolAddress((void**)&pf4, g_f4);

    k_embed1<<<NODES, 128>>>(x1, x2, w1, b1);
    k_embed2<<<NODES, 128>>>(w2, b2);

    for (int l = 0; l < 3; l++) {
        k_gat_h<<<NODES / 4, 128>>>(gat_w, gat_as, gat_ad, l);
        k_init_m<<<(NODES + 255) / 256, 256>>>();
        k_edge_max<<<(ETOT + 255) / 256, 256>>>(dei, pei);
        k_self_den<<<(NODES + 255) / 256, 256>>>();
        k_edge_den<<<(ETOT + 255) / 256, 256>>>(dei, pei);
        k_self_out<<<(NODES * HIDD + 255) / 256, 256>>>(gat_b, l);
        k_edge_out<<<(ETOT * 32 + 255) / 256, 256>>>(dei, pei);
        k_relu_accum<<<(NODES * HIDD + 255) / 256, 256>>>(l);
    }

    k_rowsum<<<(NODES * 32 + 255) / 256, 256>>>();
    k_cbuf<<<(BSZ * SEIN + 255) / 256, 256>>>();

    k_initbias<<<(BSZ * SEHID + 255) / 256, 256>>>(pc1, se1_b, SEHID);
    k_skinny<<<dim3((SEHID + 255) / 256, 20), 256>>>(pc, se1_w, pc1, SEIN, SEHID);
    k_act<<<(BSZ * SEHID + 255) / 256, 256>>>(pc1, BSZ * SEHID, 1);

    k_initbias<<<(BSZ * SEIN + 255) / 256, 256>>>(pc2, se2_b, SEIN);
    k_skinny<<<dim3((SEIN + 255) / 256, 4), 256>>>(pc1, se2_w, pc2, SEHID, SEIN);
    k_act<<<(BSZ * SEIN + 255) / 256, 256>>>(pc2, BSZ * SEIN, 2);

    k_wl<<<(BSZ * LL1 * 32 + 255) / 256, 256>>>(inter);
    k_wp<<<(BSZ * LL2 * 32 + 255) / 256, 256>>>(inter);
    k_fuse<<<BSZ, 256>>>();

    k_dense<<<BSZ, 128>>>(pxx, fc1_w, fc1_b, dout + 32, pf1, 256, 512, 1);
    k_dense<<<BSZ, 128>>>(pf1, fc2_w, fc2_b, nullptr, pf2, 512, 256, 1);
    k_dense<<<BSZ, 128>>>(pf2, fc3_w, fc3_b, nullptr, pf3, 256, 128, 1);
    k_dense<<<BSZ, 128>>>(pf3, fc4_w, fc4_b, nullptr, pf4, 128, 64, 1);
    k_dense<<<BSZ, 64>>>(pf4, out_w, out_b, nullptr, dout, 64, 1, 0);
}

// round 3
// speedup vs baseline: 1.4662x; 1.4662x over previous
#include <cuda_runtime.h>
#include <math.h>

#define NODES 8672
#define ND    2528
#define HIDD  128
#define BSZ   32
#define LL1   79
#define LL2   192
#define E1T   5120
#define E2T   12800
#define ETOT  17920
#define SEIN  15168
#define SEHID 2000
#define SEK   271      // 79 + 192

// ---------------- device scratch ----------------
__device__ float g_x   [NODES*HIDD];
__device__ float g_h   [NODES*HIDD];
__device__ float g_o   [NODES*HIDD];     // unnormalized numerator
__device__ float g_xsum[NODES*HIDD];
__device__ float g_hs[NODES], g_hd[NODES], g_den[NODES];
__device__ float g_rs[NODES];            // row sums / 256
__device__ float g_sew[SEK*SEHID];       // [0:79) WL rows, [79:271) WP rows
__device__ float g_c1[BSZ*SEHID];
__device__ float g_c2[BSZ*SEIN];
__device__ float g_wl[BSZ*LL1], g_wp[BSZ*LL2];
__device__ float g_xx[BSZ*256];
__device__ float g_f1[BSZ*512], g_f2[BSZ*256], g_f3[BSZ*128], g_f4[BSZ*64];

__device__ __forceinline__ float lrelu(float x) { return x > 0.f ? x : 0.2f * x; }

// ---- f32x2 helpers ----
__device__ __forceinline__ void fma2(unsigned long long& d, unsigned long long a, unsigned long long b) {
    asm("fma.rn.f32x2 %0, %1, %2, %0;" : "+l"(d) : "l"(a), "l"(b));
}
__device__ __forceinline__ unsigned long long pack2(float x, float y) {
    unsigned long long r;
    asm("mov.b64 %0, {%1, %2};" : "=l"(r) : "f"(x), "f"(y));
    return r;
}
__device__ __forceinline__ void unpack2(unsigned long long v, float& x, float& y) {
    asm("mov.b64 {%0, %1}, %2;" : "=f"(x), "=f"(y) : "l"(v));
}
__device__ __forceinline__ void lds_v2u64(unsigned saddr, unsigned long long& a, unsigned long long& b) {
    asm volatile("ld.shared.v2.u64 {%0,%1}, [%2];" : "=l"(a), "=l"(b) : "r"(saddr));
}

// ---------------- fused embedding MLP (8 rows / block) ----------------
__global__ void k_embed(const float* __restrict__ x1, const float* __restrict__ x2,
                        const float* __restrict__ w1, const float* __restrict__ b1,
                        const float* __restrict__ w2, const float* __restrict__ b2) {
    __shared__ float xsT[52][8];
    __shared__ float hbT[128][8];
    int tid = threadIdx.x;
    int r0 = blockIdx.x * 8;
    for (int idx = tid; idx < 8 * 52; idx += 128) {
        int r = idx / 52, c = idx - r * 52;
        int row = r0 + r;
        xsT[c][r] = (row < ND) ? x1[row * 52 + c] : x2[(row - ND) * 52 + c];
    }
    __syncthreads();
    float acc[8] = {0.f,0.f,0.f,0.f,0.f,0.f,0.f,0.f};
    for (int k = 0; k < 52; k++) {
        float w = w1[k * 128 + tid];
        float4 a0 = *(const float4*)&xsT[k][0];
        float4 a1 = *(const float4*)&xsT[k][4];
        acc[0] = fmaf(a0.x, w, acc[0]); acc[1] = fmaf(a0.y, w, acc[1]);
        acc[2] = fmaf(a0.z, w, acc[2]); acc[3] = fmaf(a0.w, w, acc[3]);
        acc[4] = fmaf(a1.x, w, acc[4]); acc[5] = fmaf(a1.y, w, acc[5]);
        acc[6] = fmaf(a1.z, w, acc[6]); acc[7] = fmaf(a1.w, w, acc[7]);
    }
    float bv = b1[tid];
#pragma unroll
    for (int r = 0; r < 8; r++) hbT[tid][r] = fmaxf(acc[r] + bv, 0.f);
    __syncthreads();
    float a2[8] = {0.f,0.f,0.f,0.f,0.f,0.f,0.f,0.f};
    for (int k = 0; k < 128; k++) {
        float w = w2[k * 128 + tid];
        float4 a0 = *(const float4*)&hbT[k][0];
        float4 a1 = *(const float4*)&hbT[k][4];
        a2[0] = fmaf(a0.x, w, a2[0]); a2[1] = fmaf(a0.y, w, a2[1]);
        a2[2] = fmaf(a0.z, w, a2[2]); a2[3] = fmaf(a0.w, w, a2[3]);
        a2[4] = fmaf(a1.x, w, a2[4]); a2[5] = fmaf(a1.y, w, a2[5]);
        a2[6] = fmaf(a1.z, w, a2[6]); a2[7] = fmaf(a1.w, w, a2[7]);
    }
    float b2v = b2[tid];
#pragma unroll
    for (int r = 0; r < 8; r++)
        g_x[(r0 + r) * 128 + tid] = fmaxf(a2[r] + b2v, 0.f);
}

// ---------------- GAT: h = x@W, attn dots, self-loop init ----------------
__global__ void k_gat_h(const float* __restrict__ gat_w, const float* __restrict__ gat_as,
                        const float* __restrict__ gat_ad, int layer) {
    __shared__ float xsT[128][8];
    __shared__ float redS[8][4], redD[8][4];
    __shared__ float sws[8];
    int tid = threadIdx.x;
    int r0 = blockIdx.x * 8;
    for (int idx = tid; idx < 1024; idx += 128) {
        int r = idx >> 7, k = idx & 127;
        xsT[k][r] = g_x[(r0 + r) * 128 + k];
    }
    __syncthreads();
    int widx = (r0 < ND ? 0 : 3) + layer;
    const float* W = gat_w + (size_t)widx * 16384;
    float acc[8] = {0.f,0.f,0.f,0.f,0.f,0.f,0.f,0.f};
    for (int k = 0; k < 128; k++) {
        float w = W[k * 128 + tid];
        float4 a0 = *(const float4*)&xsT[k][0];
        float4 a1 = *(const float4*)&xsT[k][4];
        acc[0] = fmaf(a0.x, w, acc[0]); acc[1] = fmaf(a0.y, w, acc[1]);
        acc[2] = fmaf(a0.z, w, acc[2]); acc[3] = fmaf(a0.w, w, acc[3]);
        acc[4] = fmaf(a1.x, w, acc[4]); acc[5] = fmaf(a1.y, w, acc[5]);
        acc[6] = fmaf(a1.z, w, acc[6]); acc[7] = fmaf(a1.w, w, acc[7]);
    }
    float asv = gat_as[widx * 128 + tid], adv = gat_ad[widx * 128 + tid];
    int lane = tid & 31, wrp = tid >> 5;
#pragma unroll
    for (int r = 0; r < 8; r++) {
        float ps = acc[r] * asv, pd = acc[r] * adv;
#pragma unroll
        for (int o = 16; o > 0; o >>= 1) {
            ps += __shfl_down_sync(0xffffffffu, ps, o);
            pd += __shfl_down_sync(0xffffffffu, pd, o);
        }
        if (lane == 0) { redS[r][wrp] = ps; redD[r][wrp] = pd; }
    }
    __syncthreads();
    if (tid < 8) {
        float hs = redS[tid][0] + redS[tid][1] + redS[tid][2] + redS[tid][3];
        float hd = redD[tid][0] + redD[tid][1] + redD[tid][2] + redD[tid][3];
        g_hs[r0 + tid] = hs; g_hd[r0 + tid] = hd;
        float w = expf(lrelu(hs + hd));   // self-loop weight (no max shift needed)
        g_den[r0 + tid] = w;
        sws[tid] = w;
    }
    __syncthreads();
#pragma unroll
    for (int r = 0; r < 8; r++) {
        g_h[(r0 + r) * 128 + tid] = acc[r];
        g_o[(r0 + r) * 128 + tid] = sws[r] * acc[r];
    }
}

// per-edge: accumulate unnormalized numerator + denominator in ONE pass
__global__ void k_edge(const int* __restrict__ dei, const int* __restrict__ pei) {
    int gid = blockIdx.x * blockDim.x + threadIdx.x;
    int e = gid >> 5, lane = gid & 31;
    if (e >= ETOT) return;
    int s, d;
    if (e < E1T) { s = dei[e]; d = dei[E1T + e]; }
    else { int q = e - E1T; s = pei[q] + ND; d = pei[E2T + q] + ND; }
    float w = 0.f;
    if (lane == 0) {
        w = expf(lrelu(g_hs[s] + g_hd[d]));
        atomicAdd(&g_den[d], w);
    }
    w = __shfl_sync(0xffffffffu, w, 0);
#pragma unroll
    for (int c = 0; c < 4; c++) {
        int f = lane + 32 * c;
        atomicAdd(&g_o[d * 128 + f], w * g_h[s * 128 + f]);
    }
}

// normalize + bias + relu + residual accum; last layer also does row sums
__global__ void k_final(const float* __restrict__ gat_b, int layer) {
    int gid = blockIdx.x * blockDim.x + threadIdx.x;
    int n = gid >> 5, lane = gid & 31;
    if (n >= NODES) return;
    int widx = (n < ND ? 0 : 3) + layer;
    float inv = 1.0f / g_den[n];
    float4 o = ((const float4*)&g_o[n * 128])[lane];
    float4 b = ((const float4*)&gat_b[widx * 128])[lane];
    float4 v;
    v.x = fmaxf(fmaf(o.x, inv, b.x), 0.f);
    v.y = fmaxf(fmaf(o.y, inv, b.y), 0.f);
    v.z = fmaxf(fmaf(o.z, inv, b.z), 0.f);
    v.w = fmaxf(fmaf(o.w, inv, b.w), 0.f);
    float4* xs4 = (float4*)&g_xsum[n * 128];
    float4 sum;
    if (layer == 0) sum = v;
    else {
        float4 p = xs4[lane];
        sum.x = p.x + v.x; sum.y = p.y + v.y; sum.z = p.z + v.z; sum.w = p.w + v.w;
    }
    xs4[lane] = sum;
    if (layer < 2) ((float4*)&g_x[n * 128])[lane] = v;
    else {
        float s = sum.x + sum.y + sum.z + sum.w;
#pragma unroll
        for (int o2 = 16; o2 > 0; o2 >>= 1) s += __shfl_down_sync(0xffffffffu, s, o2);
        if (lane == 0) g_rs[n] = s * (1.f / 256.f);
    }
}

// ---------------- SE layer 1 via weight reduction ----------------
// WL[i,n] = sum_j W[(i*192+j), n]   (rows 0..78 of g_sew)
__global__ void k_wredL(const float* __restrict__ W1) {
    int n = blockIdx.x * 128 + threadIdx.x;
    if (n >= SEHID) return;
    int i0 = blockIdx.y * 8;
#pragma unroll
    for (int ii = 0; ii < 8; ii++) {
        int i = i0 + ii;
        if (i >= LL1) break;
        const float* p = W1 + (size_t)(i * 192) * SEHID + n;
        float acc = 0.f;
#pragma unroll 8
        for (int j = 0; j < 192; j++) acc += p[(size_t)j * SEHID];
        g_sew[i * SEHID + n] = acc;
    }
}
// WP[j,n] = sum_i W[(i*192+j), n]   (rows 79..270 of g_sew)
__global__ void k_wredP(const float* __restrict__ W1) {
    int n = blockIdx.x * 128 + threadIdx.x;
    if (n >= SEHID) return;
    int j0 = blockIdx.y * 8;
#pragma unroll
    for (int jj = 0; jj < 8; jj++) {
        int j = j0 + jj;
        const float* p = W1 + (size_t)j * SEHID + n;
        float acc = 0.f;
#pragma unroll 4
        for (int i = 0; i < LL1; i++) acc += p[(size_t)(i * 192) * SEHID];
        g_sew[(LL1 + j) * SEHID + n] = acc;
    }
}

// c1(32,2000) = [rl|rp](32,271) @ g_sew(271,2000) + b ; f32x2, row-paired
__global__ void k_se1(const float* __restrict__ bias) {
    __shared__ float AsT[SEK][36];
    int tid = threadIdx.x;
    int n = blockIdx.x * 128 + tid;
    for (int idx = tid; idx < 32 * SEK; idx += 128) {
        int m = idx / SEK, k = idx - m * SEK;
        float v = (k < LL1) ? g_rs[m * LL1 + k] : g_rs[ND + m * LL2 + (k - LL1)];
        AsT[k][m] = v;
    }
    __syncthreads();
    if (n >= SEHID) return;
    float bn = bias[n];
    unsigned long long acc[16];
    unsigned long long bp = pack2(bn, bn);
#pragma unroll
    for (int q = 0; q < 16; q++) acc[q] = bp;
    unsigned sbase = (unsigned)__cvta_generic_to_shared(&AsT[0][0]);
#pragma unroll 4
    for (int k = 0; k < SEK; k++) {
        float w = g_sew[k * SEHID + n];
        unsigned long long w2 = pack2(w, w);
        unsigned row = sbase + (unsigned)k * 144;
#pragma unroll
        for (int q = 0; q < 8; q++) {
            unsigned long long a0, a1;
            lds_v2u64(row + q * 16, a0, a1);
            fma2(acc[2 * q], a0, w2);
            fma2(acc[2 * q + 1], a1, w2);
        }
    }
#pragma unroll
    for (int q = 0; q < 16; q++) {
        float lo, hi; unpack2(acc[q], lo, hi);
        g_c1[(2 * q) * SEHID + n] = lo;
        g_c1[(2 * q + 1) * SEHID + n] = hi;
    }
}

__global__ void k_initc2(const float* __restrict__ bias) {
    int idx = blockIdx.x * blockDim.x + threadIdx.x;
    if (idx < BSZ * SEIN) g_c2[idx] = bias[idx % SEIN];
}

// c2 += relu(c1) @ se2_w ; f32x2, split-K=2, relu folded into A-load
#define TK2 50
__global__ void k_se2(const float* __restrict__ W) {
    __shared__ float AsT[TK2][36];
    int tid = threadIdx.x;
    int n = blockIdx.x * 128 + tid;
    int k0 = blockIdx.y * 1000;
    bool valid = (n < SEIN);
    unsigned long long acc[16];
#pragma unroll
    for (int q = 0; q < 16; q++) acc[q] = 0ULL;
    unsigned sbase = (unsigned)__cvta_generic_to_shared(&AsT[0][0]);
    for (int kk = k0; kk < k0 + 1000; kk += TK2) {
        __syncthreads();
        for (int idx = tid; idx < 32 * TK2; idx += 128) {
            int m = idx / TK2, t = idx - m * TK2;
            AsT[t][m] = fmaxf(g_c1[m * SEHID + kk + t], 0.f);
        }
        __syncthreads();
        if (valid) {
            const float* wp = W + (size_t)kk * SEIN + n;
#pragma unroll 5
            for (int t = 0; t < TK2; t++) {
                float w = wp[(size_t)t * SEIN];
                unsigned long long w2 = pack2(w, w);
                unsigned row = sbase + (unsigned)t * 144;
#pragma unroll
                for (int q = 0; q < 8; q++) {
                    unsigned long long a0, a1;
                    lds_v2u64(row + q * 16, a0, a1);
                    fma2(acc[2 * q], a0, w2);
                    fma2(acc[2 * q + 1], a1, w2);
                }
            }
        }
    }
    if (valid) {
#pragma unroll
        for (int q = 0; q < 16; q++) {
            float lo, hi; unpack2(acc[q], lo, hi);
            atomicAdd(&g_c2[(size_t)(2 * q) * SEIN + n], lo);
            atomicAdd(&g_c2[(size_t)(2 * q + 1) * SEIN + n], hi);
        }
    }
}

// sigmoid folded; wl[b,i] and wp[b,j] weighted sums
__global__ void k_wlp(const float* __restrict__ inter) {
    int gid = blockIdx.x * blockDim.x + threadIdx.x;
    int w = gid >> 5, lane = gid & 31;
    if (w < BSZ * LL1) {
        int b = w / LL1, i = w - b * LL1;
        float s = 0.f;
        for (int j = lane; j < LL2; j += 32) {
            int idx = b * SEIN + i * LL2 + j;
            float sg = 1.f / (1.f + expf(-g_c2[idx]));
            s += sg / inter[idx];
        }
#pragma unroll
        for (int o = 16; o > 0; o >>= 1) s += __shfl_down_sync(0xffffffffu, s, o);
        if (lane == 0) g_wl[w] = s * (1.f / (float)SEIN);
    } else if (w < BSZ * (LL1 + LL2)) {
        int w2i = w - BSZ * LL1;
        int b = w2i / LL2, j = w2i - b * LL2;
        float s = 0.f;
        for (int i = lane; i < LL1; i += 32) {
            int idx = b * SEIN + i * LL2 + j;
            float sg = 1.f / (1.f + expf(-g_c2[idx]));
            s += sg / inter[idx];
        }
#pragma unroll
        for (int o = 16; o > 0; o >>= 1) s += __shfl_down_sync(0xffffffffu, s, o);
        if (lane == 0) g_wp[w2i] = s * (1.f / (float)SEIN);
    }
}

__global__ void k_fuse() {
    int b = blockIdx.x, t = threadIdx.x;
    float acc = 0.f;
    if (t < HIDD) {
        for (int i = 0; i < LL1; i++)
            acc = fmaf(g_wl[b * LL1 + i], g_xsum[(b * LL1 + i) * HIDD + t], acc);
    } else {
        int h = t - HIDD;
        for (int j = 0; j < LL2; j++)
            acc = fmaf(g_wp[b * LL2 + j], g_xsum[(ND + b * LL2 + j) * HIDD + h], acc);
    }
    g_xx[b * 256 + t] = acc;
}

// ---------------- head MLP ----------------
__global__ void k_dense(const float* __restrict__ in, const float* __restrict__ W,
                        const float* __restrict__ bias, float* __restrict__ out_pre,
                        float* __restrict__ out_act, int K, int N, int act) {
    int row = blockIdx.x;
    __shared__ float xs[512];
    for (int k = threadIdx.x; k < K; k += blockDim.x) xs[k] = in[row * K + k];
    __syncthreads();
    for (int n = threadIdx.x; n < N; n += blockDim.x) {
        float acc = bias[n];
        for (int k = 0; k < K; k++) acc = fmaf(xs[k], W[k * N + n], acc);
        if (out_pre) out_pre[row * N + n] = acc;
        if (act == 1) acc = fmaxf(acc, 0.f);
        if (out_act) out_act[row * N + n] = acc;
    }
}

extern "C" void kernel_launch(void* const* d_in, const int* in_sizes, int n_in,
                              void* d_out, int out_size) {
    const float* x1    = (const float*)d_in[0];
    const float* x2    = (const float*)d_in[1];
    const float* inter = (const float*)d_in[2];
    const int*   dei   = (const int*)d_in[3];
    const int*   pei   = (const int*)d_in[4];
    const float* w1    = (const float*)d_in[5];
    const float* b1    = (const float*)d_in[6];
    const float* w2    = (const float*)d_in[7];
    const float* b2    = (const float*)d_in[8];
    const float* gat_w = (const float*)d_in[9];
    const float* gat_as= (const float*)d_in[10];
    const float* gat_ad= (const float*)d_in[11];
    const float* gat_b = (const float*)d_in[12];
    const float* se1_w = (const float*)d_in[13];
    const float* se1_b = (const float*)d_in[14];
    const float* se2_w = (const float*)d_in[15];
    const float* se2_b = (const float*)d_in[16];
    const float* fc1_w = (const float*)d_in[17];
    const float* fc1_b = (const float*)d_in[18];
    const float* fc2_w = (const float*)d_in[19];
    const float* fc2_b = (const float*)d_in[20];
    const float* fc3_w = (const float*)d_in[21];
    const float* fc3_b = (const float*)d_in[22];
    const float* fc4_w = (const float*)d_in[23];
    const float* fc4_b = (const float*)d_in[24];
    const float* out_w = (const float*)d_in[25];
    const float* out_b = (const float*)d_in[26];
    float* dout = (float*)d_out;

    float *pxx, *pf1, *pf2, *pf3, *pf4;
    cudaGetSymbolAddress((void**)&pxx, g_xx);
    cudaGetSymbolAddress((void**)&pf1, g_f1);
    cudaGetSymbolAddress((void**)&pf2, g_f2);
    cudaGetSymbolAddress((void**)&pf3, g_f3);
    cudaGetSymbolAddress((void**)&pf4, g_f4);

    k_embed<<<NODES / 8, 128>>>(x1, x2, w1, b1, w2, b2);

    for (int l = 0; l < 3; l++) {
        k_gat_h<<<NODES / 8, 128>>>(gat_w, gat_as, gat_ad, l);
        k_edge<<<(ETOT * 32 + 255) / 256, 256>>>(dei, pei);
        k_final<<<(NODES * 32 + 255) / 256, 256>>>(gat_b, l);
    }

    k_wredL<<<dim3(16, 10), 128>>>(se1_w);
    k_wredP<<<dim3(16, 24), 128>>>(se1_w);
    k_se1<<<16, 128>>>(se1_b);

    k_initc2<<<(BSZ * SEIN + 255) / 256, 256>>>(se2_b);
    k_se2<<<dim3(119, 2), 128>>>(se2_w);

    k_wlp<<<(BSZ * (LL1 + LL2) * 32 + 255) / 256, 256>>>(inter);
    k_fuse<<<BSZ, 256>>>();

    k_dense<<<BSZ, 128>>>(pxx, fc1_w, fc1_b, dout + 32, pf1, 256, 512, 1);
    k_dense<<<BSZ, 128>>>(pf1, fc2_w, fc2_b, nullptr, pf2, 512, 256, 1);
    k_dense<<<BSZ, 128>>>(pf2, fc3_w, fc3_b, nullptr, pf3, 256, 128, 1);
    k_dense<<<BSZ, 128>>>(pf3, fc4_w, fc4_b, nullptr, pf4, 128, 64, 1);
    k_dense<<<BSZ, 64>>>(pf4, out_w, out_b, nullptr, dout, 64, 1, 0);
}

// round 8
// speedup vs baseline: 3.1796x; 2.1686x over previous
#include <cuda_runtime.h>
#include <math.h>

#define NODES 8672
#define ND    2528
#define HIDD  128
#define BSZ   32
#define LL1   79
#define LL2   192
#define E1T   5120
#define E2T   12800
#define ETOT  17920
#define SEIN  15168
#define SEHID 2000
#define SEK   271      // 79 + 192

// ---------------- device scratch ----------------
__device__ float g_x   [NODES*HIDD];
__device__ float g_h   [NODES*HIDD];
__device__ float g_o   [NODES*HIDD];     // unnormalized numerator
__device__ float g_xsum[NODES*HIDD];
__device__ float g_hs[NODES], g_hd[NODES], g_den[NODES];
__device__ float g_rs[NODES];            // row sums / 256
__device__ float g_sew[SEK*SEHID];       // [0:79) WL rows, [79:271) WP rows
__device__ float g_c1[BSZ*SEHID];
__device__ float g_c2[BSZ*SEIN];
__device__ float g_wl[BSZ*LL1], g_wp[BSZ*LL2];
__device__ float g_xx[BSZ*256];

__device__ __forceinline__ float lrelu(float x) { return x > 0.f ? x : 0.2f * x; }

// ---- f32x2 helpers ----
__device__ __forceinline__ void fma2(unsigned long long& d, unsigned long long a, unsigned long long b) {
    asm("fma.rn.f32x2 %0, %1, %2, %0;" : "+l"(d) : "l"(a), "l"(b));
}
__device__ __forceinline__ unsigned long long pack2(float x, float y) {
    unsigned long long r;
    asm("mov.b64 %0, {%1, %2};" : "=l"(r) : "f"(x), "f"(y));
    return r;
}
__device__ __forceinline__ void unpack2(unsigned long long v, float& x, float& y) {
    asm("mov.b64 {%0, %1}, %2;" : "=f"(x), "=f"(y) : "l"(v));
}
__device__ __forceinline__ void lds_v2u64(unsigned saddr, unsigned long long& a, unsigned long long& b) {
    asm volatile("ld.shared.v2.u64 {%0,%1}, [%2];" : "=l"(a), "=l"(b) : "r"(saddr));
}

// ---------------- fused embedding MLP (8 rows / block) ----------------
__global__ void k_embed(const float* __restrict__ x1, const float* __restrict__ x2,
                        const float* __restrict__ w1, const float* __restrict__ b1,
                        const float* __restrict__ w2, const float* __restrict__ b2) {
    __shared__ float xsT[52][8];
    __shared__ float hbT[128][8];
    int tid = threadIdx.x;
    int r0 = blockIdx.x * 8;
    for (int idx = tid; idx < 8 * 52; idx += 128) {
        int r = idx / 52, c = idx - r * 52;
        int row = r0 + r;
        xsT[c][r] = (row < ND) ? x1[row * 52 + c] : x2[(row - ND) * 52 + c];
    }
    __syncthreads();
    float acc[8] = {0.f,0.f,0.f,0.f,0.f,0.f,0.f,0.f};
    for (int k = 0; k < 52; k++) {
        float w = w1[k * 128 + tid];
        float4 a0 = *(const float4*)&xsT[k][0];
        float4 a1 = *(const float4*)&xsT[k][4];
        acc[0] = fmaf(a0.x, w, acc[0]); acc[1] = fmaf(a0.y, w, acc[1]);
        acc[2] = fmaf(a0.z, w, acc[2]); acc[3] = fmaf(a0.w, w, acc[3]);
        acc[4] = fmaf(a1.x, w, acc[4]); acc[5] = fmaf(a1.y, w, acc[5]);
        acc[6] = fmaf(a1.z, w, acc[6]); acc[7] = fmaf(a1.w, w, acc[7]);
    }
    float bv = b1[tid];
#pragma unroll
    for (int r = 0; r < 8; r++) hbT[tid][r] = fmaxf(acc[r] + bv, 0.f);
    __syncthreads();
    float a2[8] = {0.f,0.f,0.f,0.f,0.f,0.f,0.f,0.f};
    for (int k = 0; k < 128; k++) {
        float w = w2[k * 128 + tid];
        float4 a0 = *(const float4*)&hbT[k][0];
        float4 a1 = *(const float4*)&hbT[k][4];
        a2[0] = fmaf(a0.x, w, a2[0]); a2[1] = fmaf(a0.y, w, a2[1]);
        a2[2] = fmaf(a0.z, w, a2[2]); a2[3] = fmaf(a0.w, w, a2[3]);
        a2[4] = fmaf(a1.x, w, a2[4]); a2[5] = fmaf(a1.y, w, a2[5]);
        a2[6] = fmaf(a1.z, w, a2[6]); a2[7] = fmaf(a1.w, w, a2[7]);
    }
    float b2v = b2[tid];
#pragma unroll
    for (int r = 0; r < 8; r++)
        g_x[(r0 + r) * 128 + tid] = fmaxf(a2[r] + b2v, 0.f);
}

// ---------------- GAT: h = x@W, attn dots, self-loop init ----------------
__global__ void k_gat_h(const float* __restrict__ gat_w, const float* __restrict__ gat_as,
                        const float* __restrict__ gat_ad, int layer) {
    __shared__ float xsT[128][8];
    __shared__ float redS[8][4], redD[8][4];
    __shared__ float sws[8];
    int tid = threadIdx.x;
    int r0 = blockIdx.x * 8;
    for (int idx = tid; idx < 1024; idx += 128) {
        int r = idx >> 7, k = idx & 127;
        xsT[k][r] = g_x[(r0 + r) * 128 + k];
    }
    __syncthreads();
    int widx = (r0 < ND ? 0 : 3) + layer;
    const float* W = gat_w + (size_t)widx * 16384;
    float acc[8] = {0.f,0.f,0.f,0.f,0.f,0.f,0.f,0.f};
    for (int k = 0; k < 128; k++) {
        float w = W[k * 128 + tid];
        float4 a0 = *(const float4*)&xsT[k][0];
        float4 a1 = *(const float4*)&xsT[k][4];
        acc[0] = fmaf(a0.x, w, acc[0]); acc[1] = fmaf(a0.y, w, acc[1]);
        acc[2] = fmaf(a0.z, w, acc[2]); acc[3] = fmaf(a0.w, w, acc[3]);
        acc[4] = fmaf(a1.x, w, acc[4]); acc[5] = fmaf(a1.y, w, acc[5]);
        acc[6] = fmaf(a1.z, w, acc[6]); acc[7] = fmaf(a1.w, w, acc[7]);
    }
    float asv = gat_as[widx * 128 + tid], adv = gat_ad[widx * 128 + tid];
    int lane = tid & 31, wrp = tid >> 5;
#pragma unroll
    for (int r = 0; r < 8; r++) {
        float ps = acc[r] * asv, pd = acc[r] * adv;
#pragma unroll
        for (int o = 16; o > 0; o >>= 1) {
            ps += __shfl_down_sync(0xffffffffu, ps, o);
            pd += __shfl_down_sync(0xffffffffu, pd, o);
        }
        if (lane == 0) { redS[r][wrp] = ps; redD[r][wrp] = pd; }
    }
    __syncthreads();
    if (tid < 8) {
        float hs = redS[tid][0] + redS[tid][1] + redS[tid][2] + redS[tid][3];
        float hd = redD[tid][0] + redD[tid][1] + redD[tid][2] + redD[tid][3];
        g_hs[r0 + tid] = hs; g_hd[r0 + tid] = hd;
        float w = expf(lrelu(hs + hd));   // self-loop weight (shift-free softmax)
        g_den[r0 + tid] = w;
        sws[tid] = w;
    }
    __syncthreads();
#pragma unroll
    for (int r = 0; r < 8; r++) {
        g_h[(r0 + r) * 128 + tid] = acc[r];
        g_o[(r0 + r) * 128 + tid] = sws[r] * acc[r];
    }
}

// per-edge: accumulate unnormalized numerator + denominator in ONE pass
__global__ void k_edge(const int* __restrict__ dei, const int* __restrict__ pei) {
    int gid = blockIdx.x * blockDim.x + threadIdx.x;
    int e = gid >> 5, lane = gid & 31;
    if (e >= ETOT) return;
    int s, d;
    if (e < E1T) { s = dei[e]; d = dei[E1T + e]; }
    else { int q = e - E1T; s = pei[q] + ND; d = pei[E2T + q] + ND; }
    float w = 0.f;
    if (lane == 0) {
        w = expf(lrelu(g_hs[s] + g_hd[d]));
        atomicAdd(&g_den[d], w);
    }
    w = __shfl_sync(0xffffffffu, w, 0);
#pragma unroll
    for (int c = 0; c < 4; c++) {
        int f = lane + 32 * c;
        atomicAdd(&g_o[d * 128 + f], w * g_h[s * 128 + f]);
    }
}

// normalize + bias + relu + residual accum; last layer also does row sums
__global__ void k_final(const float* __restrict__ gat_b, int layer) {
    int gid = blockIdx.x * blockDim.x + threadIdx.x;
    int n = gid >> 5, lane = gid & 31;
    if (n >= NODES) return;
    int widx = (n < ND ? 0 : 3) + layer;
    float inv = 1.0f / g_den[n];
    float4 o = ((const float4*)&g_o[n * 128])[lane];
    float4 b = ((const float4*)&gat_b[widx * 128])[lane];
    float4 v;
    v.x = fmaxf(fmaf(o.x, inv, b.x), 0.f);
    v.y = fmaxf(fmaf(o.y, inv, b.y), 0.f);
    v.z = fmaxf(fmaf(o.z, inv, b.z), 0.f);
    v.w = fmaxf(fmaf(o.w, inv, b.w), 0.f);
    float4* xs4 = (float4*)&g_xsum[n * 128];
    float4 sum;
    if (layer == 0) sum = v;
    else {
        float4 p = xs4[lane];
        sum.x = p.x + v.x; sum.y = p.y + v.y; sum.z = p.z + v.z; sum.w = p.w + v.w;
    }
    xs4[lane] = sum;
    if (layer < 2) ((float4*)&g_x[n * 128])[lane] = v;
    else {
        float s = sum.x + sum.y + sum.z + sum.w;
#pragma unroll
        for (int o2 = 16; o2 > 0; o2 >>= 1) s += __shfl_down_sync(0xffffffffu, s, o2);
        if (lane == 0) g_rs[n] = s * (1.f / 256.f);
    }
}

// ---------------- SE layer 1 weight reductions (parallelism-first) ----------------
// WL[i,n] = sum_j W[(i*192+j), n] ; grid (16 ncol, 79 i) = 1264 blocks
__global__ void k_wredL(const float* __restrict__ W1) {
    int n = blockIdx.x * 128 + threadIdx.x;
    if (n >= SEHID) return;
    int i = blockIdx.y;
    const float* p = W1 + (size_t)(i * 192) * SEHID + n;
    float a0 = 0.f, a1 = 0.f, a2 = 0.f, a3 = 0.f;
#pragma unroll 2
    for (int j = 0; j < 192; j += 8) {
        a0 += p[(size_t)(j+0) * SEHID] + p[(size_t)(j+4) * SEHID];
        a1 += p[(size_t)(j+1) * SEHID] + p[(size_t)(j+5) * SEHID];
        a2 += p[(size_t)(j+2) * SEHID] + p[(size_t)(j+6) * SEHID];
        a3 += p[(size_t)(j+3) * SEHID] + p[(size_t)(j+7) * SEHID];
    }
    g_sew[i * SEHID + n] = (a0 + a1) + (a2 + a3);
}
// WP[j,n] = sum_i W[(i*192+j), n] ; grid (16 ncol, 192 j) = 3072 blocks
__global__ void k_wredP(const float* __restrict__ W1) {
    int n = blockIdx.x * 128 + threadIdx.x;
    if (n >= SEHID) return;
    int j = blockIdx.y;
    const float* p = W1 + (size_t)j * SEHID + n;
    const size_t S = (size_t)192 * SEHID;
    float a0 = 0.f, a1 = 0.f, a2 = 0.f, a3 = 0.f;
    int i = 0;
#pragma unroll 2
    for (; i + 8 <= LL1; i += 8) {
        a0 += p[(i+0) * S] + p[(i+4) * S];
        a1 += p[(i+1) * S] + p[(i+5) * S];
        a2 += p[(i+2) * S] + p[(i+6) * S];
        a3 += p[(i+3) * S] + p[(i+7) * S];
    }
    for (; i < LL1; i++) a0 += p[i * S];
    g_sew[(LL1 + j) * SEHID + n] = (a0 + a1) + (a2 + a3);
}

// c1(32,2000) = [rl|rp](32,271) @ g_sew(271,2000) + b ; f32x2, row-paired
__global__ void k_se1(const float* __restrict__ bias) {
    __shared__ float AsT[SEK][36];
    int tid = threadIdx.x;
    int n = blockIdx.x * 128 + tid;
    for (int idx = tid; idx < 32 * SEK; idx += 128) {
        int m = idx / SEK, k = idx - m * SEK;
        float v = (k < LL1) ? g_rs[m * LL1 + k] : g_rs[ND + m * LL2 + (k - LL1)];
        AsT[k][m] = v;
    }
    __syncthreads();
    if (n >= SEHID) return;
    float bn = bias[n];
    unsigned long long acc[16];
    unsigned long long bp = pack2(bn, bn);
#pragma unroll
    for (int q = 0; q < 16; q++) acc[q] = bp;
    unsigned sbase = (unsigned)__cvta_generic_to_shared(&AsT[0][0]);
#pragma unroll 4
    for (int k = 0; k < SEK; k++) {
        float w = g_sew[k * SEHID + n];
        unsigned long long w2 = pack2(w, w);
        unsigned row = sbase + (unsigned)k * 144;
#pragma unroll
        for (int q = 0; q < 8; q++) {
            unsigned long long a0, a1;
            lds_v2u64(row + q * 16, a0, a1);
            fma2(acc[2 * q], a0, w2);
            fma2(acc[2 * q + 1], a1, w2);
        }
    }
#pragma unroll
    for (int q = 0; q < 16; q++) {
        float lo, hi; unpack2(acc[q], lo, hi);
        g_c1[(2 * q) * SEHID + n] = lo;
        g_c1[(2 * q + 1) * SEHID + n] = hi;
    }
}

__global__ void k_initc2(const float* __restrict__ bias) {
    int idx = blockIdx.x * blockDim.x + threadIdx.x;
    if (idx < BSZ * SEIN) g_c2[idx] = bias[idx % SEIN];
}

// c2 += relu(c1) @ se2_w ; f32x2, split-K=8 (chunks of 250)
#define TK2 50
__global__ void k_se2(const float* __restrict__ W) {
    __shared__ float AsT[TK2][36];
    int tid = threadIdx.x;
    int n = blockIdx.x * 128 + tid;
    int k0 = blockIdx.y * 250;
    bool valid = (n < SEIN);
    unsigned long long acc[16];
#pragma unroll
    for (int q = 0; q < 16; q++) acc[q] = 0ULL;
    unsigned sbase = (unsigned)__cvta_generic_to_shared(&AsT[0][0]);
    for (int kk = k0; kk < k0 + 250; kk += TK2) {
        __syncthreads();
        for (int idx = tid; idx < 32 * TK2; idx += 128) {
            int m = idx / TK2, t = idx - m * TK2;
            AsT[t][m] = fmaxf(g_c1[m * SEHID + kk + t], 0.f);
        }
        __syncthreads();
        if (valid) {
            const float* wp = W + (size_t)kk * SEIN + n;
#pragma unroll 5
            for (int t = 0; t < TK2; t++) {
                float w = wp[(size_t)t * SEIN];
                unsigned long long w2 = pack2(w, w);
                unsigned row = sbase + (unsigned)t * 144;
#pragma unroll
                for (int q = 0; q < 8; q++) {
                    unsigned long long a0, a1;
                    lds_v2u64(row + q * 16, a0, a1);
                    fma2(acc[2 * q], a0, w2);
                    fma2(acc[2 * q + 1], a1, w2);
                }
            }
        }
    }
    if (valid) {
#pragma unroll
        for (int q = 0; q < 16; q++) {
            float lo, hi; unpack2(acc[q], lo, hi);
            atomicAdd(&g_c2[(size_t)(2 * q) * SEIN + n], lo);
            atomicAdd(&g_c2[(size_t)(2 * q + 1) * SEIN + n], hi);
        }
    }
}

// sigmoid folded; wl[b,i] and wp[b,j] weighted sums
__global__ void k_wlp(const float* __restrict__ inter) {
    int gid = blockIdx.x * blockDim.x + threadIdx.x;
    int w = gid >> 5, lane = gid & 31;
    if (w < BSZ * LL1) {
        int b = w / LL1, i = w - b * LL1;
        float s = 0.f;
        for (int j = lane; j < LL2; j += 32) {
            int idx = b * SEIN + i * LL2 + j;
            float sg = 1.f / (1.f + expf(-g_c2[idx]));
            s += sg / inter[idx];
        }
#pragma unroll
        for (int o = 16; o > 0; o >>= 1) s += __shfl_down_sync(0xffffffffu, s, o);
        if (lane == 0) g_wl[w] = s * (1.f / (float)SEIN);
    } else if (w < BSZ * (LL1 + LL2)) {
        int w2i = w - BSZ * LL1;
        int b = w2i / LL2, j = w2i - b * LL2;
        float s = 0.f;
        for (int i = lane; i < LL1; i += 32) {
            int idx = b * SEIN + i * LL2 + j;
            float sg = 1.f / (1.f + expf(-g_c2[idx]));
            s += sg / inter[idx];
        }
#pragma unroll
        for (int o = 16; o > 0; o >>= 1) s += __shfl_down_sync(0xffffffffu, s, o);
        if (lane == 0) g_wp[w2i] = s * (1.f / (float)SEIN);
    }
}

__global__ void k_fuse() {
    int b = blockIdx.x, t = threadIdx.x;
    float acc = 0.f;
    if (t < HIDD) {
        for (int i = 0; i < LL1; i++)
            acc = fmaf(g_wl[b * LL1 + i], g_xsum[(b * LL1 + i) * HIDD + t], acc);
    } else {
        int h = t - HIDD;
        for (int j = 0; j < LL2; j++)
            acc = fmaf(g_wp[b * LL2 + j], g_xsum[(ND + b * LL2 + j) * HIDD + h], acc);
    }
    g_xx[b * 256 + t] = acc;
}

// ---------------- fused head MLP: one block per batch row ----------------
__global__ void __launch_bounds__(512) k_head(
    const float* __restrict__ fc1_w, const float* __restrict__ fc1_b,
    const float* __restrict__ fc2_w, const float* __restrict__ fc2_b,
    const float* __restrict__ fc3_w, const float* __restrict__ fc3_b,
    const float* __restrict__ fc4_w, const float* __restrict__ fc4_b,
    const float* __restrict__ out_w, const float* __restrict__ out_b,
    float* __restrict__ dout) {
    int b = blockIdx.x, t = threadIdx.x;
    __shared__ float s0[256], s1[512], s2[256], s3[128], s4[64];
    if (t < 256) s0[t] = g_xx[b * 256 + t];
    __syncthreads();
    // fc1: 256 -> 512 (h1 pre-relu is an output)
    {
        float acc = fc1_b[t];
        for (int k = 0; k < 256; k++) acc = fmaf(s0[k], fc1_w[k * 512 + t], acc);
        dout[32 + b * 512 + t] = acc;
        s1[t] = fmaxf(acc, 0.f);
    }
    __syncthreads();
    // fc2: 512 -> 256
    if (t < 256) {
        float acc = fc2_b[t];
        for (int k = 0; k < 512; k++) acc = fmaf(s1[k], fc2_w[k * 256 + t], acc);
        s2[t] = fmaxf(acc, 0.f);
    }
    __syncthreads();
    // fc3: 256 -> 128
    if (t < 128) {
        float acc = fc3_b[t];
        for (int k = 0; k < 256; k++) acc = fmaf(s2[k], fc3_w[k * 128 + t], acc);
        s3[t] = fmaxf(acc, 0.f);
    }
    __syncthreads();
    // fc4: 128 -> 64
    if (t < 64) {
        float acc = fc4_b[t];
        for (int k = 0; k < 128; k++) acc = fmaf(s3[k], fc4_w[k * 64 + t], acc);
        s4[t] = fmaxf(acc, 0.f);
    }
    __syncthreads();
    // out: 64 -> 1
    if (t < 32) {
        float acc = s4[t] * out_w[t] + s4[t + 32] * out_w[t + 32];
#pragma unroll
        for (int o = 16; o > 0; o >>= 1) acc += __shfl_down_sync(0xffffffffu, acc, o);
        if (t == 0) dout[b] = acc + out_b[0];
    }
}

extern "C" void kernel_launch(void* const* d_in, const int* in_sizes, int n_in,
                              void* d_out, int out_size) {
    const float* x1    = (const float*)d_in[0];
    const float* x2    = (const float*)d_in[1];
    const float* inter = (const float*)d_in[2];
    const int*   dei   = (const int*)d_in[3];
    const int*   pei   = (const int*)d_in[4];
    const float* w1    = (const float*)d_in[5];
    const float* b1    = (const float*)d_in[6];
    const float* w2    = (const float*)d_in[7];
    const float* b2    = (const float*)d_in[8];
    const float* gat_w = (const float*)d_in[9];
    const float* gat_as= (const float*)d_in[10];
    const float* gat_ad= (const float*)d_in[11];
    const float* gat_b = (const float*)d_in[12];
    const float* se1_w = (const float*)d_in[13];
    const float* se1_b = (const float*)d_in[14];
    const float* se2_w = (const float*)d_in[15];
    const float* se2_b = (const float*)d_in[16];
    const float* fc1_w = (const float*)d_in[17];
    const float* fc1_b = (const float*)d_in[18];
    const float* fc2_w = (const float*)d_in[19];
    const float* fc2_b = (const float*)d_in[20];
    const float* fc3_w = (const float*)d_in[21];
    const float* fc3_b = (const float*)d_in[22];
    const float* fc4_w = (const float*)d_in[23];
    const float* fc4_b = (const float*)d_in[24];
    const float* out_w = (const float*)d_in[25];
    const float* out_b = (const float*)d_in[26];
    float* dout = (float*)d_out;

    k_embed<<<NODES / 8, 128>>>(x1, x2, w1, b1, w2, b2);

    for (int l = 0; l < 3; l++) {
        k_gat_h<<<NODES / 8, 128>>>(gat_w, gat_as, gat_ad, l);
        k_edge<<<(ETOT * 32 + 255) / 256, 256>>>(dei, pei);
        k_final<<<(NODES * 32 + 255) / 256, 256>>>(gat_b, l);
    }

    k_wredL<<<dim3(16, LL1), 128>>>(se1_w);
    k_wredP<<<dim3(16, LL2), 128>>>(se1_w);
    k_se1<<<16, 128>>>(se1_b);

    k_initc2<<<(BSZ * SEIN + 255) / 256, 256>>>(se2_b);
    k_se2<<<dim3(119, 8), 128>>>(se2_w);

    k_wlp<<<(BSZ * (LL1 + LL2) * 32 + 255) / 256, 256>>>(inter);
    k_fuse<<<BSZ, 256>>>();

    k_head<<<BSZ, 512>>>(fc1_w, fc1_b, fc2_w, fc2_b, fc3_w, fc3_b,
                         fc4_w, fc4_b, out_w, out_b, dout);
}